// round 4
// baseline (speedup 1.0000x reference)
#include <cuda_runtime.h>
#include <cstdint>

// Fixed shapes per reference
static constexpr int Bn    = 512;      // batch
static constexpr int Ln    = 8192;     // doc length
static constexpr int Nn    = 128;      // output_sentence_num
static constexpr int Sn    = 256;      // output_sentence_len
static constexpr int DELIM = 5;
static constexpr int TPB   = 256;      // threads per block
static constexpr int TOKS  = Ln / TPB; // 32 tokens/thread == one bitmask word
static constexpr int NW    = TPB / 32; // 8 warps
static constexpr int SPLIT = 4;        // CTAs per row (emit split)
static constexpr int KSEG  = Nn / SPLIT; // 32 segments per CTA

__global__ void zero_len(float* __restrict__ len_f)
{
    if (threadIdx.x < Bn) len_f[threadIdx.x] = 0.0f;
}

// d_out (float32): [ otp(B*N*S) | len_doc(B) | mask(B*N*S) ]
__global__ __launch_bounds__(TPB, 8)
void split_kernel(const int* __restrict__ x, float* __restrict__ out)
{
    __shared__ int s_dpos[Nn - 1];   // positions of first 127 delimiters
    __shared__ int s_woff[NW];       // per-warp scan offsets
    __shared__ int s_D;              // total delimiter count
    __shared__ int s_doc;            // nonempty sentences (this CTA's share)

    const int sp   = blockIdx.x;     // which quarter of segments
    const int b    = blockIdx.y;     // row
    const int t    = threadIdx.x;
    const int lane = t & 31;
    const int warp = t >> 5;

    if (t == 0) s_doc = 0;

    const int* __restrict__ xrow = x + (size_t)b * Ln;

    // ---- Pass 1: load 32 tokens (8 x int4), build delimiter bitmask ----
    const int base = t * TOKS;
    const int4* __restrict__ x4 = reinterpret_cast<const int4*>(xrow + base);

    unsigned dmask = 0;
    #pragma unroll
    for (int i = 0; i < TOKS / 4; i++) {
        int4 v = x4[i];
        dmask |= (unsigned)(v.x == DELIM) << (4 * i + 0);
        dmask |= (unsigned)(v.y == DELIM) << (4 * i + 1);
        dmask |= (unsigned)(v.z == DELIM) << (4 * i + 2);
        dmask |= (unsigned)(v.w == DELIM) << (4 * i + 3);
    }
    const int cnt = __popc(dmask);

    // warp inclusive scan of counts
    int incl = cnt;
    #pragma unroll
    for (int o = 1; o < 32; o <<= 1) {
        int n = __shfl_up_sync(0xffffffffu, incl, o);
        if (lane >= o) incl += n;
    }
    if (lane == 31) s_woff[warp] = incl;
    __syncthreads();

    if (warp == 0 && lane < NW) {
        int my  = s_woff[lane];
        int inc = my;
        #pragma unroll
        for (int o = 1; o < NW; o <<= 1) {
            int n = __shfl_up_sync((1u << NW) - 1u, inc, o);
            if (lane >= o) inc += n;
        }
        s_woff[lane] = inc - my;      // exclusive warp offset
        if (lane == NW - 1) s_D = inc;
    }
    __syncthreads();

    const int excl = incl - cnt + s_woff[warp];

    // ---- Pass 2: record first 127 delimiter positions from the bitmask ----
    if (dmask && excl < Nn - 1) {
        int r = excl;
        unsigned m = dmask;
        while (m && r < Nn - 1) {
            int bit = __ffs(m) - 1;
            s_dpos[r++] = base + bit;
            m &= m - 1;
        }
    }
    __syncthreads();

    const int D = s_D;

    float* __restrict__ otp_f  = out;
    float* __restrict__ len_f  = out + (size_t)Bn * Nn * Sn;
    float* __restrict__ mask_f = len_f + Bn;

    // ---- Emit: this CTA covers segments [sp*KSEG, sp*KSEG+KSEG), one/warp ----
    int doc_local = 0;
    #pragma unroll 1
    for (int kk = warp; kk < KSEG; kk += NW) {
        const int k = sp * KSEG + kk;
        int start = 0, size = 0;
        if (k <= D) {
            start = (k == 0) ? 0 : (s_dpos[k - 1] + 1);
            if (k == Nn - 1 || k == D) size = (Ln + 1) - start;  // tail-merged / last
            else                        size = s_dpos[k] + 1 - start;
        }
        const bool ws = (size > 1);   // lone-delimiter chunk -> all PAD

        const size_t row_off = ((size_t)b * Nn + k) * Sn;
        float4* __restrict__ otp4  = reinterpret_cast<float4*>(otp_f  + row_off);
        float4* __restrict__ mask4 = reinterpret_cast<float4*>(mask_f + row_off);

        int nz = 0;
        if (ws) {   // warp-uniform branch; loads unconditional + predicated select
            #pragma unroll
            for (int i = 0; i < Sn / 128; i++) {      // 2 iters of 128 slots
                const int s0 = i * 128 + lane * 4;
                const int j  = start + s0;
                // clamped, always-valid addresses -> 4 independent LDGs
                int r0 = xrow[min(j,     Ln - 1)];
                int r1 = xrow[min(j + 1, Ln - 1)];
                int r2 = xrow[min(j + 2, Ln - 1)];
                int r3 = xrow[min(j + 3, Ln - 1)];
                int v0 = (s0     < size) ? ((j     < Ln) ? r0 : DELIM) : 0;
                int v1 = (s0 + 1 < size) ? ((j + 1 < Ln) ? r1 : DELIM) : 0;
                int v2 = (s0 + 2 < size) ? ((j + 2 < Ln) ? r2 : DELIM) : 0;
                int v3 = (s0 + 3 < size) ? ((j + 3 < Ln) ? r3 : DELIM) : 0;
                nz += (v0 != 0) + (v1 != 0) + (v2 != 0) + (v3 != 0);
                otp4[i * 32 + lane] =
                    make_float4((float)v0, (float)v1, (float)v2, (float)v3);
            }
        } else {
            #pragma unroll
            for (int i = 0; i < Sn / 128; i++)
                otp4[i * 32 + lane] = make_float4(0.f, 0.f, 0.f, 0.f);
        }

        // warp-reduce nonzero count -> len_sent
        #pragma unroll
        for (int o = 16; o > 0; o >>= 1) nz += __shfl_down_sync(0xffffffffu, nz, o);
        nz = __shfl_sync(0xffffffffu, nz, 0);
        if (lane == 0 && nz > 0) doc_local++;

        #pragma unroll
        for (int i = 0; i < Sn / 128; i++) {
            const int s0 = i * 128 + lane * 4;
            mask4[i * 32 + lane] = make_float4(
                (s0     < nz) ? 1.0f : 0.0f,
                (s0 + 1 < nz) ? 1.0f : 0.0f,
                (s0 + 2 < nz) ? 1.0f : 0.0f,
                (s0 + 3 < nz) ? 1.0f : 0.0f);
        }
    }

    if (lane == 0 && doc_local > 0) atomicAdd(&s_doc, doc_local);
    __syncthreads();
    if (t == 0 && s_doc > 0) atomicAdd(&len_f[b], (float)s_doc);
}

extern "C" void kernel_launch(void* const* d_in, const int* in_sizes, int n_in,
                              void* d_out, int out_size)
{
    const int* x  = (const int*)d_in[0];
    float* out    = (float*)d_out;
    float* len_f  = out + (size_t)Bn * Nn * Sn;

    zero_len<<<1, 512>>>(len_f);
    split_kernel<<<dim3(SPLIT, Bn), TPB>>>(x, out);
}

// round 5
// speedup vs baseline: 1.1590x; 1.1590x over previous
#include <cuda_runtime.h>
#include <cstdint>

// Fixed shapes per reference
static constexpr int Bn    = 512;      // batch
static constexpr int Ln    = 8192;     // doc length
static constexpr int Nn    = 128;      // output_sentence_num
static constexpr int Sn    = 256;      // output_sentence_len
static constexpr int DELIM = 5;
static constexpr int TPB   = 256;      // threads per block
static constexpr int TOKS  = Ln / TPB; // 32 tokens/thread == one bitmask word
static constexpr int NW    = TPB / 32; // 8 warps
static constexpr int SEG_PER_CTA = 8;  // emit: one warp per segment

// Scratch: per-(row,segment) {start, size}
__device__ int2 g_seg[Bn * Nn];

// ---------------- Phase A: scan rows, build segment table ----------------
__global__ __launch_bounds__(TPB, 6)
void scan_kernel(const int* __restrict__ x, float* __restrict__ len_f)
{
    __shared__ int s_dpos[Nn - 1];   // positions of first 127 delimiters
    __shared__ int s_woff[NW];
    __shared__ int s_D;

    const int b    = blockIdx.x;
    const int t    = threadIdx.x;
    const int lane = t & 31;
    const int warp = t >> 5;

    const int* __restrict__ xrow = x + (size_t)b * Ln;

    // load 32 tokens (8 x int4), build delimiter bitmask
    const int base = t * TOKS;
    const int4* __restrict__ x4 = reinterpret_cast<const int4*>(xrow + base);

    unsigned dmask = 0;
    #pragma unroll
    for (int i = 0; i < TOKS / 4; i++) {
        int4 v = x4[i];
        dmask |= (unsigned)(v.x == DELIM) << (4 * i + 0);
        dmask |= (unsigned)(v.y == DELIM) << (4 * i + 1);
        dmask |= (unsigned)(v.z == DELIM) << (4 * i + 2);
        dmask |= (unsigned)(v.w == DELIM) << (4 * i + 3);
    }
    const int cnt = __popc(dmask);

    // warp inclusive scan
    int incl = cnt;
    #pragma unroll
    for (int o = 1; o < 32; o <<= 1) {
        int n = __shfl_up_sync(0xffffffffu, incl, o);
        if (lane >= o) incl += n;
    }
    if (lane == 31) s_woff[warp] = incl;
    __syncthreads();

    if (warp == 0 && lane < NW) {
        int my  = s_woff[lane];
        int inc = my;
        #pragma unroll
        for (int o = 1; o < NW; o <<= 1) {
            int n = __shfl_up_sync((1u << NW) - 1u, inc, o);
            if (lane >= o) inc += n;
        }
        s_woff[lane] = inc - my;
        if (lane == NW - 1) s_D = inc;
    }
    __syncthreads();

    const int excl = incl - cnt + s_woff[warp];

    // record first 127 delimiter positions
    if (dmask && excl < Nn - 1) {
        int r = excl;
        unsigned m = dmask;
        while (m && r < Nn - 1) {
            int bit = __ffs(m) - 1;
            s_dpos[r++] = base + bit;
            m &= m - 1;
        }
    }
    __syncthreads();

    const int D = s_D;

    // threads 0..127 emit segment descriptors
    if (t < Nn) {
        const int k = t;
        int start = 0, size = 0;
        if (k <= D) {
            start = (k == 0) ? 0 : (s_dpos[k - 1] + 1);
            if (k == Nn - 1 || k == D) size = (Ln + 1) - start;  // tail-merged / last
            else                        size = s_dpos[k] + 1 - start;
        }
        g_seg[b * Nn + k] = make_int2(start, size);
    }
    if (t == 0) len_f[b] = 0.0f;   // zero len_doc for phase B atomics
}

// ---------------- Phase B: emit, one warp per segment ----------------
__global__ __launch_bounds__(TPB, 8)
void emit_kernel(const int* __restrict__ x, float* __restrict__ out)
{
    __shared__ int s_doc;

    const int b    = blockIdx.y;
    const int t    = threadIdx.x;
    const int lane = t & 31;
    const int warp = t >> 5;
    const int k    = blockIdx.x * SEG_PER_CTA + warp;

    if (t == 0) s_doc = 0;
    __syncthreads();

    const int* __restrict__ xrow = x + (size_t)b * Ln;

    const int2 seg  = g_seg[b * Nn + k];
    const int start = seg.x;
    const int size  = seg.y;
    const bool ws   = (size > 1);   // lone-delimiter / unused -> all PAD

    float* __restrict__ otp_f  = out;
    float* __restrict__ len_f  = out + (size_t)Bn * Nn * Sn;
    float* __restrict__ mask_f = len_f + Bn;

    const size_t row_off = ((size_t)b * Nn + k) * Sn;
    float4* __restrict__ otp4  = reinterpret_cast<float4*>(otp_f  + row_off);
    float4* __restrict__ mask4 = reinterpret_cast<float4*>(mask_f + row_off);

    int nz = 0;
    if (ws) {
        #pragma unroll
        for (int i = 0; i < Sn / 128; i++) {          // 2 iters of 128 slots
            const int s0 = i * 128 + lane * 4;
            const int j  = start + s0;
            // per-element predicated loads: only real tokens touch memory
            int v0 = 0, v1 = 0, v2 = 0, v3 = 0;
            if (s0     < size) v0 = (j     < Ln) ? xrow[j]     : DELIM;
            if (s0 + 1 < size) v1 = (j + 1 < Ln) ? xrow[j + 1] : DELIM;
            if (s0 + 2 < size) v2 = (j + 2 < Ln) ? xrow[j + 2] : DELIM;
            if (s0 + 3 < size) v3 = (j + 3 < Ln) ? xrow[j + 3] : DELIM;
            nz += (v0 != 0) + (v1 != 0) + (v2 != 0) + (v3 != 0);
            otp4[i * 32 + lane] =
                make_float4((float)v0, (float)v1, (float)v2, (float)v3);
        }
    } else {
        #pragma unroll
        for (int i = 0; i < Sn / 128; i++)
            otp4[i * 32 + lane] = make_float4(0.f, 0.f, 0.f, 0.f);
    }

    // warp-reduce nonzero count -> len_sent
    #pragma unroll
    for (int o = 16; o > 0; o >>= 1) nz += __shfl_down_sync(0xffffffffu, nz, o);
    nz = __shfl_sync(0xffffffffu, nz, 0);

    #pragma unroll
    for (int i = 0; i < Sn / 128; i++) {
        const int s0 = i * 128 + lane * 4;
        mask4[i * 32 + lane] = make_float4(
            (s0     < nz) ? 1.0f : 0.0f,
            (s0 + 1 < nz) ? 1.0f : 0.0f,
            (s0 + 2 < nz) ? 1.0f : 0.0f,
            (s0 + 3 < nz) ? 1.0f : 0.0f);
    }

    if (lane == 0 && nz > 0) atomicAdd(&s_doc, 1);
    __syncthreads();
    if (t == 0 && s_doc > 0) atomicAdd(&len_f[b], (float)s_doc);
}

extern "C" void kernel_launch(void* const* d_in, const int* in_sizes, int n_in,
                              void* d_out, int out_size)
{
    const int* x  = (const int*)d_in[0];
    float* out    = (float*)d_out;
    float* len_f  = out + (size_t)Bn * Nn * Sn;

    scan_kernel<<<Bn, TPB>>>(x, len_f);
    emit_kernel<<<dim3(Nn / SEG_PER_CTA, Bn), TPB>>>(x, out);
}

// round 6
// speedup vs baseline: 1.1973x; 1.0330x over previous
#include <cuda_runtime.h>
#include <cstdint>

// Fixed shapes per reference
static constexpr int Bn    = 512;      // batch
static constexpr int Ln    = 8192;     // doc length
static constexpr int Nn    = 128;      // output_sentence_num
static constexpr int Sn    = 256;      // output_sentence_len
static constexpr int DELIM = 5;
static constexpr int TPB   = 512;      // threads per block
static constexpr int TOKS  = Ln / TPB; // 16 tokens/thread == one 16-bit mask
static constexpr int NW    = TPB / 32; // 16 warps

// d_out (float32): [ otp(B*N*S) | len_doc(B) | mask(B*N*S) ]
__global__ __launch_bounds__(TPB, 4)
void split_kernel(const int* __restrict__ x, float* __restrict__ out)
{
    __shared__ int s_dpos[Nn - 1];   // positions of first 127 delimiters
    __shared__ int s_woff[NW];       // per-warp scan offsets
    __shared__ int s_D;              // total delimiter count
    __shared__ int s_doc;            // # nonempty sentences

    const int b    = blockIdx.x;
    const int t    = threadIdx.x;
    const int lane = t & 31;
    const int warp = t >> 5;

    if (t == 0) s_doc = 0;

    const int* __restrict__ xrow = x + (size_t)b * Ln;

    // ---- Pass 1: load 16 tokens (4 x int4), build 16-bit delimiter mask ----
    const int base = t * TOKS;
    const int4* __restrict__ x4 = reinterpret_cast<const int4*>(xrow + base);

    unsigned dmask = 0;
    #pragma unroll
    for (int i = 0; i < TOKS / 4; i++) {
        int4 v = x4[i];
        dmask |= (unsigned)(v.x == DELIM) << (4 * i + 0);
        dmask |= (unsigned)(v.y == DELIM) << (4 * i + 1);
        dmask |= (unsigned)(v.z == DELIM) << (4 * i + 2);
        dmask |= (unsigned)(v.w == DELIM) << (4 * i + 3);
    }
    const int cnt = __popc(dmask);

    // warp inclusive scan of counts
    int incl = cnt;
    #pragma unroll
    for (int o = 1; o < 32; o <<= 1) {
        int n = __shfl_up_sync(0xffffffffu, incl, o);
        if (lane >= o) incl += n;
    }
    if (lane == 31) s_woff[warp] = incl;
    __syncthreads();

    if (warp == 0 && lane < NW) {
        int my  = s_woff[lane];
        int inc = my;
        #pragma unroll
        for (int o = 1; o < NW; o <<= 1) {
            int n = __shfl_up_sync(0x0000ffffu, inc, o);
            if (lane >= o) inc += n;
        }
        s_woff[lane] = inc - my;      // exclusive warp offset
        if (lane == NW - 1) s_D = inc;
    }
    __syncthreads();

    const int excl = incl - cnt + s_woff[warp];

    // ---- Pass 2: record first 127 delimiter positions from the bitmask ----
    if (dmask && excl < Nn - 1) {
        int r = excl;
        unsigned m = dmask;
        while (m && r < Nn - 1) {
            int bit = __ffs(m) - 1;
            s_dpos[r++] = base + bit;
            m &= m - 1;
        }
    }
    __syncthreads();

    const int D = s_D;

    float* __restrict__ otp_f  = out;
    float* __restrict__ len_f  = out + (size_t)Bn * Nn * Sn;
    float* __restrict__ mask_f = len_f + Bn;

    // ---- Emit: one warp per segment (16 warps x 8 sweeps), float4 stores ----
    int doc_local = 0;
    #pragma unroll 1
    for (int k = warp; k < Nn; k += NW) {
        int start = 0, size = 0;
        if (k <= D) {
            start = (k == 0) ? 0 : (s_dpos[k - 1] + 1);
            if (k == Nn - 1 || k == D) size = (Ln + 1) - start;  // tail-merged / last
            else                        size = s_dpos[k] + 1 - start;
        }
        const bool ws = (size > 1);   // lone-delimiter / unused -> all PAD

        const size_t row_off = ((size_t)b * Nn + k) * Sn;
        float4* __restrict__ otp4  = reinterpret_cast<float4*>(otp_f  + row_off);
        float4* __restrict__ mask4 = reinterpret_cast<float4*>(mask_f + row_off);

        int nz = 0;
        if (ws) {   // warp-uniform branch
            #pragma unroll
            for (int i = 0; i < Sn / 128; i++) {      // 2 iters of 128 slots
                const int s0 = i * 128 + lane * 4;
                const int j  = start + s0;
                int v0 = 0, v1 = 0, v2 = 0, v3 = 0;
                if (s0     < size) v0 = (j     < Ln) ? xrow[j]     : DELIM;
                if (s0 + 1 < size) v1 = (j + 1 < Ln) ? xrow[j + 1] : DELIM;
                if (s0 + 2 < size) v2 = (j + 2 < Ln) ? xrow[j + 2] : DELIM;
                if (s0 + 3 < size) v3 = (j + 3 < Ln) ? xrow[j + 3] : DELIM;
                nz += (v0 != 0) + (v1 != 0) + (v2 != 0) + (v3 != 0);
                otp4[i * 32 + lane] =
                    make_float4((float)v0, (float)v1, (float)v2, (float)v3);
            }
        } else {
            #pragma unroll
            for (int i = 0; i < Sn / 128; i++)
                otp4[i * 32 + lane] = make_float4(0.f, 0.f, 0.f, 0.f);
        }

        // warp-reduce nonzero count -> len_sent
        #pragma unroll
        for (int o = 16; o > 0; o >>= 1) nz += __shfl_down_sync(0xffffffffu, nz, o);
        nz = __shfl_sync(0xffffffffu, nz, 0);
        if (lane == 0 && nz > 0) doc_local++;

        #pragma unroll
        for (int i = 0; i < Sn / 128; i++) {
            const int s0 = i * 128 + lane * 4;
            mask4[i * 32 + lane] = make_float4(
                (s0     < nz) ? 1.0f : 0.0f,
                (s0 + 1 < nz) ? 1.0f : 0.0f,
                (s0 + 2 < nz) ? 1.0f : 0.0f,
                (s0 + 3 < nz) ? 1.0f : 0.0f);
        }
    }

    if (lane == 0 && doc_local > 0) atomicAdd(&s_doc, doc_local);
    __syncthreads();
    if (t == 0) len_f[b] = (float)s_doc;
}

extern "C" void kernel_launch(void* const* d_in, const int* in_sizes, int n_in,
                              void* d_out, int out_size)
{
    const int* x = (const int*)d_in[0];
    split_kernel<<<Bn, TPB>>>(x, (float*)d_out);
}

// round 7
// speedup vs baseline: 1.2482x; 1.0426x over previous
#include <cuda_runtime.h>
#include <cstdint>

// Fixed shapes per reference
static constexpr int Bn    = 512;      // batch
static constexpr int Ln    = 8192;     // doc length
static constexpr int Nn    = 128;      // output_sentence_num
static constexpr int Sn    = 256;      // output_sentence_len
static constexpr int DELIM = 5;
static constexpr int TPB   = 512;      // threads per block
static constexpr int TOKS  = Ln / TPB; // 16 tokens/thread
static constexpr int NW    = TPB / 32; // 16 warps

// exact int->float for 0 <= v < 2^23 without I2F (IADD + FADD)
__device__ __forceinline__ float i2f_small(int v)
{
    return __int_as_float(0x4B000000 + v) - 8388608.0f;
}

// d_out (float32): [ otp(B*N*S) | len_doc(B) | mask(B*N*S) ]
__global__ __launch_bounds__(TPB, 4)
void split_kernel(const int* __restrict__ x, float* __restrict__ out)
{
    __shared__ int s_dpos[Nn - 1];   // positions of first 127 delimiters
    __shared__ int s_woff[NW];       // per-warp scan offsets
    __shared__ int s_D;              // total delimiter count
    __shared__ int s_doc;            // # nonempty sentences

    const int b    = blockIdx.x;
    const int t    = threadIdx.x;
    const int lane = t & 31;
    const int warp = t >> 5;

    if (t == 0) s_doc = 0;

    const int* __restrict__ xrow = x + (size_t)b * Ln;

    // ---- Pass 1: load 16 tokens (4 x int4), build 16-bit delimiter mask ----
    const int base = t * TOKS;
    const int4* __restrict__ x4 = reinterpret_cast<const int4*>(xrow + base);

    unsigned dmask = 0;
    #pragma unroll
    for (int i = 0; i < TOKS / 4; i++) {
        int4 v = x4[i];
        dmask |= (unsigned)(v.x == DELIM) << (4 * i + 0);
        dmask |= (unsigned)(v.y == DELIM) << (4 * i + 1);
        dmask |= (unsigned)(v.z == DELIM) << (4 * i + 2);
        dmask |= (unsigned)(v.w == DELIM) << (4 * i + 3);
    }
    const int cnt = __popc(dmask);

    // warp inclusive scan of counts
    int incl = cnt;
    #pragma unroll
    for (int o = 1; o < 32; o <<= 1) {
        int n = __shfl_up_sync(0xffffffffu, incl, o);
        if (lane >= o) incl += n;
    }
    if (lane == 31) s_woff[warp] = incl;
    __syncthreads();

    if (warp == 0 && lane < NW) {
        int my  = s_woff[lane];
        int inc = my;
        #pragma unroll
        for (int o = 1; o < NW; o <<= 1) {
            int n = __shfl_up_sync(0x0000ffffu, inc, o);
            if (lane >= o) inc += n;
        }
        s_woff[lane] = inc - my;      // exclusive warp offset
        if (lane == NW - 1) s_D = inc;
    }
    __syncthreads();

    const int excl = incl - cnt + s_woff[warp];

    // ---- Pass 2: record first 127 delimiter positions from the bitmask ----
    if (dmask && excl < Nn - 1) {
        int r = excl;
        unsigned m = dmask;
        while (m && r < Nn - 1) {
            int bit = __ffs(m) - 1;
            s_dpos[r++] = base + bit;
            m &= m - 1;
        }
    }
    __syncthreads();

    const int D = s_D;

    float* __restrict__ otp_f  = out;
    float* __restrict__ len_f  = out + (size_t)Bn * Nn * Sn;
    float* __restrict__ mask_f = len_f + Bn;

    // ---- Emit: one warp per segment, branch-free unified body ----
    int doc_local = 0;
    #pragma unroll 1
    for (int k = warp; k < Nn; k += NW) {
        int start = 0, size = 0;
        if (k <= D) {
            start = (k == 0) ? 0 : (s_dpos[k - 1] + 1);
            if (k == Nn - 1 || k == D) size = (Ln + 1) - start;  // tail-merged / last
            else                        size = s_dpos[k] + 1 - start;
        }
        if (size <= 1) size = 0;   // lone-delimiter / unused -> all PAD

        const size_t row_off = ((size_t)b * Nn + k) * Sn;
        float4* __restrict__ otp4  = reinterpret_cast<float4*>(otp_f  + row_off);
        float4* __restrict__ mask4 = reinterpret_cast<float4*>(mask_f + row_off);

        // all 8 loads issued up front -> 8-deep MLP
        int v[8];
        #pragma unroll
        for (int i = 0; i < 2; i++) {
            #pragma unroll
            for (int c = 0; c < 4; c++) {
                const int s = i * 128 + lane * 4 + c;
                const int j = start + s;
                int val = 0;
                if (s < size) val = (j < Ln) ? xrow[j] : DELIM;
                v[i * 4 + c] = val;
            }
        }

        int nz = (v[0] != 0) + (v[1] != 0) + (v[2] != 0) + (v[3] != 0)
               + (v[4] != 0) + (v[5] != 0) + (v[6] != 0) + (v[7] != 0);
        nz = __reduce_add_sync(0xffffffffu, nz);
        if (lane == 0 && nz > 0) doc_local++;

        #pragma unroll
        for (int i = 0; i < 2; i++) {
            otp4[i * 32 + lane] = make_float4(
                i2f_small(v[i * 4 + 0]), i2f_small(v[i * 4 + 1]),
                i2f_small(v[i * 4 + 2]), i2f_small(v[i * 4 + 3]));
        }
        #pragma unroll
        for (int i = 0; i < 2; i++) {
            const int s0 = i * 128 + lane * 4;
            mask4[i * 32 + lane] = make_float4(
                (s0     < nz) ? 1.0f : 0.0f,
                (s0 + 1 < nz) ? 1.0f : 0.0f,
                (s0 + 2 < nz) ? 1.0f : 0.0f,
                (s0 + 3 < nz) ? 1.0f : 0.0f);
        }
    }

    if (lane == 0 && doc_local > 0) atomicAdd(&s_doc, doc_local);
    __syncthreads();
    if (t == 0) len_f[b] = (float)s_doc;
}

extern "C" void kernel_launch(void* const* d_in, const int* in_sizes, int n_in,
                              void* d_out, int out_size)
{
    const int* x = (const int*)d_in[0];
    split_kernel<<<Bn, TPB>>>(x, (float*)d_out);
}

// round 8
// speedup vs baseline: 1.2636x; 1.0123x over previous
#include <cuda_runtime.h>
#include <cstdint>

// Fixed shapes per reference
static constexpr int Bn    = 512;      // batch
static constexpr int Ln    = 8192;     // doc length
static constexpr int Nn    = 128;      // output_sentence_num
static constexpr int Sn    = 256;      // output_sentence_len
static constexpr int DELIM = 5;
static constexpr int TPB   = 512;      // threads per block
static constexpr int TOKS  = Ln / TPB; // 16 tokens/thread
static constexpr int NW    = TPB / 32; // 16 warps

// exact int->float for 0 <= v < 2^23 without I2F (IADD + FADD)
__device__ __forceinline__ float i2f_small(int v)
{
    return __int_as_float(0x4B000000 + v) - 8388608.0f;
}

// d_out (float32): [ otp(B*N*S) | len_doc(B) | mask(B*N*S) ]
__global__ __launch_bounds__(TPB, 4)
void split_kernel(const int* __restrict__ x, float* __restrict__ out)
{
    __shared__ int s_dpos[Nn - 1];   // positions of first 127 delimiters
    __shared__ int s_woff[NW];       // per-warp scan offsets
    __shared__ int s_D;              // total delimiter count
    __shared__ int s_doc;            // # nonempty sentences

    const int b    = blockIdx.x;
    const int t    = threadIdx.x;
    const int lane = t & 31;
    const int warp = t >> 5;

    if (t == 0) s_doc = 0;

    const int* __restrict__ xrow = x + (size_t)b * Ln;

    // ---- Pass 1: load 16 tokens (4 x int4), build 16-bit delimiter mask ----
    const int base = t * TOKS;
    const int4* __restrict__ x4 = reinterpret_cast<const int4*>(xrow + base);

    unsigned dmask = 0;
    #pragma unroll
    for (int i = 0; i < TOKS / 4; i++) {
        int4 v = x4[i];
        dmask |= (unsigned)(v.x == DELIM) << (4 * i + 0);
        dmask |= (unsigned)(v.y == DELIM) << (4 * i + 1);
        dmask |= (unsigned)(v.z == DELIM) << (4 * i + 2);
        dmask |= (unsigned)(v.w == DELIM) << (4 * i + 3);
    }
    const int cnt = __popc(dmask);

    // warp inclusive scan of counts
    int incl = cnt;
    #pragma unroll
    for (int o = 1; o < 32; o <<= 1) {
        int n = __shfl_up_sync(0xffffffffu, incl, o);
        if (lane >= o) incl += n;
    }
    if (lane == 31) s_woff[warp] = incl;
    __syncthreads();

    if (warp == 0 && lane < NW) {
        int my  = s_woff[lane];
        int inc = my;
        #pragma unroll
        for (int o = 1; o < NW; o <<= 1) {
            int n = __shfl_up_sync(0x0000ffffu, inc, o);
            if (lane >= o) inc += n;
        }
        s_woff[lane] = inc - my;      // exclusive warp offset
        if (lane == NW - 1) s_D = inc;
    }
    __syncthreads();

    const int excl = incl - cnt + s_woff[warp];

    // ---- Pass 2: record first 127 delimiter positions from the bitmask ----
    if (dmask && excl < Nn - 1) {
        int r = excl;
        unsigned m = dmask;
        while (m && r < Nn - 1) {
            int bit = __ffs(m) - 1;
            s_dpos[r++] = base + bit;
            m &= m - 1;
        }
    }
    __syncthreads();

    const int D = s_D;

    float* __restrict__ otp_f  = out;
    float* __restrict__ len_f  = out + (size_t)Bn * Nn * Sn;
    float* __restrict__ mask_f = len_f + Bn;

    // ---- Emit: one warp per segment; stride-1 coalesced loads+otp stores ----
    int doc_local = 0;
    #pragma unroll 1
    for (int k = warp; k < Nn; k += NW) {
        int start = 0, size = 0;
        if (k <= D) {
            start = (k == 0) ? 0 : (s_dpos[k - 1] + 1);
            if (k == Nn - 1 || k == D) size = (Ln + 1) - start;  // tail-merged / last
            else                        size = s_dpos[k] + 1 - start;
        }
        if (size <= 1) size = 0;   // lone-delimiter / unused -> all PAD

        const size_t row_off = ((size_t)b * Nn + k) * Sn;
        float*  __restrict__ otp_p = otp_f + row_off;
        float4* __restrict__ mask4 = reinterpret_cast<float4*>(mask_f + row_off);

        // 8 coalesced predicated loads, all issued up front (8-deep MLP)
        int v[8];
        #pragma unroll
        for (int i = 0; i < 8; i++) {
            const int s = i * 32 + lane;          // stride-1 across warp
            const int j = start + s;
            int val = 0;
            if (s < size) val = (j < Ln) ? xrow[j] : DELIM;
            v[i] = val;
        }

        int nz = (v[0] != 0) + (v[1] != 0) + (v[2] != 0) + (v[3] != 0)
               + (v[4] != 0) + (v[5] != 0) + (v[6] != 0) + (v[7] != 0);
        nz = __reduce_add_sync(0xffffffffu, nz);
        if (lane == 0 && nz > 0) doc_local++;

        // otp: 8 coalesced STG.32 (same wavefront count as STG.128 pairs)
        #pragma unroll
        for (int i = 0; i < 8; i++)
            otp_p[i * 32 + lane] = i2f_small(v[i]);

        // mask: no load dependency -> keep vector stores
        #pragma unroll
        for (int i = 0; i < 2; i++) {
            const int s0 = i * 128 + lane * 4;
            mask4[i * 32 + lane] = make_float4(
                (s0     < nz) ? 1.0f : 0.0f,
                (s0 + 1 < nz) ? 1.0f : 0.0f,
                (s0 + 2 < nz) ? 1.0f : 0.0f,
                (s0 + 3 < nz) ? 1.0f : 0.0f);
        }
    }

    if (lane == 0 && doc_local > 0) atomicAdd(&s_doc, doc_local);
    __syncthreads();
    if (t == 0) len_f[b] = (float)s_doc;
}

extern "C" void kernel_launch(void* const* d_in, const int* in_sizes, int n_in,
                              void* d_out, int out_size)
{
    const int* x = (const int*)d_in[0];
    split_kernel<<<Bn, TPB>>>(x, (float*)d_out);
}